// round 1
// baseline (speedup 1.0000x reference)
#include <cuda_runtime.h>
#include <math.h>

#define N_NODES 100000
#define N_EDGES 1600000
#define F_IN    128
#define F_HID   64
#define F_MID   32
#define BN_EPS  1e-5f

// Scratch (alloc-free rule: __device__ globals)
__device__ float g_bufA[(size_t)N_NODES * F_HID];   // 25.6 MB
__device__ float g_bufB[(size_t)N_NODES * F_HID];   // 25.6 MB
__device__ float g_dinv[N_NODES];                   // deg -> rsqrt(deg)

// ---------------------------------------------------------------------------
// degree / normalization
// ---------------------------------------------------------------------------
__global__ void k_init_deg() {
    int i = blockIdx.x * blockDim.x + threadIdx.x;
    if (i < N_NODES) g_dinv[i] = 1.0f;              // self-loop contributes 1
}

__global__ void k_count_deg(const int* __restrict__ ei) {
    int e = blockIdx.x * blockDim.x + threadIdx.x;
    if (e < N_EDGES) atomicAdd(&g_dinv[ei[N_EDGES + e]], 1.0f);
}

__global__ void k_rsqrt_deg() {
    int i = blockIdx.x * blockDim.x + threadIdx.x;
    if (i < N_NODES) g_dinv[i] = rsqrtf(g_dinv[i]);
}

// ---------------------------------------------------------------------------
// h = X @ W   (X: [N, KDIM], W: [KDIM, 64], row-major)
// block = 256 threads, handles 64 nodes x 64 features.
// thread (f = tid&63, g = tid>>6) computes 16 nodes for feature f.
// ---------------------------------------------------------------------------
template <int KDIM>
__global__ void k_gemm(const float* __restrict__ x,
                       const float* __restrict__ W,
                       float* __restrict__ out) {
    __shared__ float Ws[KDIM * 64];
    __shared__ float Xs[64 * 32];

    int tid = threadIdx.x;
    for (int i = tid; i < KDIM * 64; i += 256) Ws[i] = W[i];

    int f = tid & 63;
    int g = tid >> 6;                 // 0..3
    int nodeBase = blockIdx.x * 64;

    float acc[16];
#pragma unroll
    for (int i = 0; i < 16; i++) acc[i] = 0.0f;

    for (int k0 = 0; k0 < KDIM; k0 += 32) {
        __syncthreads();              // also covers initial Ws load
        for (int i = tid; i < 64 * 32; i += 256) {
            int nn = i >> 5;
            int kk = i & 31;
            int gn = nodeBase + nn;
            if (gn >= N_NODES) gn = N_NODES - 1;   // clamp; result unused
            Xs[i] = x[(size_t)gn * KDIM + k0 + kk];
        }
        __syncthreads();
#pragma unroll
        for (int kk = 0; kk < 32; kk++) {
            float w = Ws[(k0 + kk) * 64 + f];
#pragma unroll
            for (int i = 0; i < 16; i++)
                acc[i] += Xs[(g * 16 + i) * 32 + kk] * w;
        }
    }

#pragma unroll
    for (int i = 0; i < 16; i++) {
        int n = nodeBase + g * 16 + i;
        if (n < N_NODES) out[(size_t)n * 64 + f] = acc[i];
    }
}

// ---------------------------------------------------------------------------
// agg = dinv^2 * h      (self-loop term; initializes the accumulator)
// ---------------------------------------------------------------------------
__global__ void k_self(const float* __restrict__ h, float* __restrict__ agg) {
    int idx = blockIdx.x * blockDim.x + threadIdx.x;
    if (idx < N_NODES * F_HID) {
        int n = idx >> 6;
        float di = g_dinv[n];
        agg[idx] = di * di * h[idx];
    }
}

// ---------------------------------------------------------------------------
// edge scatter: agg[dst] += dinv[src]*dinv[dst] * h[src]
// 16 threads per edge, each handles one float4 (4 atomics).
// ---------------------------------------------------------------------------
__global__ void k_scatter(const float* __restrict__ h,
                          const int* __restrict__ ei,
                          float* __restrict__ agg) {
    unsigned tid = blockIdx.x * blockDim.x + threadIdx.x;
    unsigned e = tid >> 4;
    if (e >= N_EDGES) return;
    int lane = tid & 15;

    int s = __ldg(ei + e);
    int d = __ldg(ei + N_EDGES + e);
    float nrm = g_dinv[s] * g_dinv[d];

    float4 v = __ldg(reinterpret_cast<const float4*>(h + (size_t)s * 64) + lane);
    float* ap = agg + (size_t)d * 64 + lane * 4;
    atomicAdd(ap + 0, nrm * v.x);
    atomicAdd(ap + 1, nrm * v.y);
    atomicAdd(ap + 2, nrm * v.z);
    atomicAdd(ap + 3, nrm * v.w);
}

// ---------------------------------------------------------------------------
// in-place: agg = relu(BN(agg + b))  [eval-mode BN]
// ---------------------------------------------------------------------------
__global__ void k_post(float* __restrict__ agg,
                       const float* __restrict__ b,
                       const float* __restrict__ g,
                       const float* __restrict__ be,
                       const float* __restrict__ m,
                       const float* __restrict__ v) {
    int idx = blockIdx.x * blockDim.x + threadIdx.x;
    if (idx < N_NODES * F_HID) {
        int f = idx & 63;
        float sc = g[f] * rsqrtf(v[f] + BN_EPS);
        float val = (agg[idx] + b[f] - m[f]) * sc + be[f];
        agg[idx] = fmaxf(val, 0.0f);
    }
}

// ---------------------------------------------------------------------------
// head: out[n] = sigmoid( relu(h @ Wc1 + bc1) @ Wc2 + bc2 )
// one warp per node; 8 nodes per 256-thread block.
// ---------------------------------------------------------------------------
__global__ void k_final(const float* __restrict__ h,
                        const float* __restrict__ Wc1,
                        const float* __restrict__ bc1,
                        const float* __restrict__ Wc2,
                        const float* __restrict__ bc2,
                        float* __restrict__ out) {
    __shared__ float W1s[64 * 32];
    __shared__ float w2s[32];
    __shared__ float b1s[32];
    __shared__ float b2s;

    int tid = threadIdx.x;
    for (int i = tid; i < 64 * 32; i += 256) W1s[i] = Wc1[i];
    if (tid < 32) { w2s[tid] = Wc2[tid]; b1s[tid] = bc1[tid]; }
    if (tid == 0) b2s = bc2[0];
    __syncthreads();

    int warp = tid >> 5;
    int lane = tid & 31;
    int n = blockIdx.x * 8 + warp;
    if (n >= N_NODES) return;

    const float* hr = h + (size_t)n * 64;
    float h0 = hr[lane];
    float h1 = hr[32 + lane];

    float acc = b1s[lane];
#pragma unroll
    for (int k = 0; k < 32; k++) {
        float hk = __shfl_sync(0xffffffffu, h0, k);
        acc += hk * W1s[k * 32 + lane];
    }
#pragma unroll
    for (int k = 0; k < 32; k++) {
        float hk = __shfl_sync(0xffffffffu, h1, k);
        acc += hk * W1s[(32 + k) * 32 + lane];
    }
    float mid = fmaxf(acc, 0.0f);
    float p = mid * w2s[lane];
#pragma unroll
    for (int off = 16; off; off >>= 1)
        p += __shfl_xor_sync(0xffffffffu, p, off);
    if (lane == 0) {
        float o = p + b2s;
        out[n] = 1.0f / (1.0f + expf(-o));
    }
}

// ---------------------------------------------------------------------------
extern "C" void kernel_launch(void* const* d_in, const int* in_sizes, int n_in,
                              void* d_out, int out_size) {
    const float* x   = (const float*)d_in[0];
    const int*   ei  = (const int*)  d_in[1];
    const float* W1  = (const float*)d_in[2];
    const float* b1  = (const float*)d_in[3];
    const float* g1  = (const float*)d_in[4];
    const float* be1 = (const float*)d_in[5];
    const float* m1  = (const float*)d_in[6];
    const float* v1  = (const float*)d_in[7];
    const float* W2  = (const float*)d_in[8];
    const float* b2  = (const float*)d_in[9];
    const float* g2  = (const float*)d_in[10];
    const float* be2 = (const float*)d_in[11];
    const float* m2  = (const float*)d_in[12];
    const float* v2  = (const float*)d_in[13];
    const float* Wc1 = (const float*)d_in[14];
    const float* bc1 = (const float*)d_in[15];
    const float* Wc2 = (const float*)d_in[16];
    const float* bc2 = (const float*)d_in[17];
    float* out = (float*)d_out;

    float* bufA;  cudaGetSymbolAddress((void**)&bufA, g_bufA);
    float* bufB;  cudaGetSymbolAddress((void**)&bufB, g_bufB);

    const int nodeBlocks   = (N_NODES + 255) / 256;           // 391
    const int edgeBlocks   = (N_EDGES + 255) / 256;           // 6250
    const int featBlocks   = (N_NODES * F_HID + 255) / 256;   // 25000
    const int gemmBlocks   = (N_NODES + 63) / 64;             // 1563
    const int scatBlocks   = (int)(((size_t)N_EDGES * 16 + 255) / 256); // 100000
    const int finalBlocks  = (N_NODES + 7) / 8;               // 12500

    // degrees / dinv
    k_init_deg<<<nodeBlocks, 256>>>();
    k_count_deg<<<edgeBlocks, 256>>>(ei);
    k_rsqrt_deg<<<nodeBlocks, 256>>>();

    // layer 1: h = x @ W1 -> bufA ; agg -> bufB
    k_gemm<F_IN><<<gemmBlocks, 256>>>(x, W1, bufA);
    k_self<<<featBlocks, 256>>>(bufA, bufB);
    k_scatter<<<scatBlocks, 256>>>(bufA, ei, bufB);
    k_post<<<featBlocks, 256>>>(bufB, b1, g1, be1, m1, v1);

    // layer 2: h = bufB @ W2 -> bufA ; agg -> bufB (bufB free after gemm)
    k_gemm<F_HID><<<gemmBlocks, 256>>>(bufB, W2, bufA);
    k_self<<<featBlocks, 256>>>(bufA, bufB);
    k_scatter<<<scatBlocks, 256>>>(bufA, ei, bufB);
    k_post<<<featBlocks, 256>>>(bufB, b2, g2, be2, m2, v2);

    // head
    k_final<<<finalBlocks, 256>>>(bufB, Wc1, bc1, Wc2, bc2, out);
}

// round 2
// speedup vs baseline: 2.0339x; 2.0339x over previous
#include <cuda_runtime.h>
#include <math.h>

#define N_NODES 100000
#define N_EDGES 1600000
#define F_IN    128
#define F_HID   64
#define BN_EPS  1e-5f

// ------------------------- scratch (__device__ globals) --------------------
__device__ float g_bufA[(size_t)N_NODES * F_HID];   // 25.6 MB
__device__ float g_bufB[(size_t)N_NODES * F_HID];   // 25.6 MB
__device__ float g_dinv[N_NODES];
__device__ int   g_cnt[N_NODES];
__device__ int   g_rowptr[N_NODES + 1];
__device__ int   g_cursor[N_NODES];
__device__ int   g_esrc[N_EDGES];
__device__ float g_ew[N_EDGES];
__device__ int   g_blksum[128];

// ------------------------- degree / CSR build ------------------------------
__global__ void k_zero_cnt() {
    int i = blockIdx.x * blockDim.x + threadIdx.x;
    if (i < N_NODES) g_cnt[i] = 0;
}

__global__ void k_hist(const int* __restrict__ ei) {
    int e = blockIdx.x * blockDim.x + threadIdx.x;
    if (e < N_EDGES) atomicAdd(&g_cnt[ei[N_EDGES + e]], 1);
}

__global__ void k_dinv() {
    int i = blockIdx.x * blockDim.x + threadIdx.x;
    if (i < N_NODES) g_dinv[i] = rsqrtf((float)g_cnt[i] + 1.0f);
}

// exclusive scan of g_cnt -> g_rowptr. Pass 1: per-block inclusive scan.
__global__ void k_scan1() {
    __shared__ int wsum[32];
    int i = blockIdx.x * 1024 + threadIdx.x;
    int lane = threadIdx.x & 31, wid = threadIdx.x >> 5;
    int v = (i < N_NODES) ? g_cnt[i] : 0;
    int sv = v;
#pragma unroll
    for (int d = 1; d < 32; d <<= 1) {
        int t = __shfl_up_sync(0xffffffffu, sv, d);
        if (lane >= d) sv += t;
    }
    if (lane == 31) wsum[wid] = sv;
    __syncthreads();
    if (wid == 0) {
        int wv = wsum[lane];
#pragma unroll
        for (int d = 1; d < 32; d <<= 1) {
            int t = __shfl_up_sync(0xffffffffu, wv, d);
            if (lane >= d) wv += t;
        }
        wsum[lane] = wv;
    }
    __syncthreads();
    int incl = sv + (wid > 0 ? wsum[wid - 1] : 0);
    if (i < N_NODES) g_rowptr[i + 1] = incl;
    if (threadIdx.x == 1023) g_blksum[blockIdx.x] = incl;
}

// Pass 2: exclusive scan of block sums (nb <= 128), single block of 128.
__global__ void k_scan2(int nb) {
    __shared__ int wsum[4];
    int b = threadIdx.x;
    int lane = b & 31, wid = b >> 5;
    int v = (b < nb) ? g_blksum[b] : 0;
    int sv = v;
#pragma unroll
    for (int d = 1; d < 32; d <<= 1) {
        int t = __shfl_up_sync(0xffffffffu, sv, d);
        if (lane >= d) sv += t;
    }
    if (lane == 31) wsum[wid] = sv;
    __syncthreads();
    if (b == 0) {
        int run = 0;
#pragma unroll
        for (int w = 0; w < 4; w++) { int t = wsum[w]; wsum[w] = run; run += t; }
    }
    __syncthreads();
    int excl = sv + wsum[wid] - v;
    if (b < nb) g_blksum[b] = excl;
}

// Pass 3: add block offsets; finalize row_ptr.
__global__ void k_scan3() {
    int i = blockIdx.x * blockDim.x + threadIdx.x;
    if (i < N_NODES) g_rowptr[i + 1] += g_blksum[i >> 10];
    if (i == 0) g_rowptr[0] = 0;
}

__global__ void k_cursor() {
    int i = blockIdx.x * blockDim.x + threadIdx.x;
    if (i < N_NODES) g_cursor[i] = g_rowptr[i];
}

__global__ void k_fill(const int* __restrict__ ei) {
    int e = blockIdx.x * blockDim.x + threadIdx.x;
    if (e >= N_EDGES) return;
    int s = ei[e];
    int d = ei[N_EDGES + e];
    int pos = atomicAdd(&g_cursor[d], 1);
    g_esrc[pos] = s;
    g_ew[pos] = g_dinv[s] * g_dinv[d];
}

// ------------------------- GEMM: out[N,64] = x[N,KDIM] @ W[KDIM,64] --------
// 256 threads, 128 nodes x 64 feats per block; thread = 4 nodes x 8 feats.
template <int KDIM>
__global__ void k_gemm(const float* __restrict__ x,
                       const float* __restrict__ W,
                       float* __restrict__ out) {
    __shared__ float Ws[32 * 64];      // 8 KB, reloaded per k-chunk
    __shared__ float Xs[128 * 33];     // 16.9 KB, padded stride 33

    int tid  = threadIdx.x;
    int fgrp = tid & 7;                // 8 feat groups x 8 feats
    int ngrp = tid >> 3;               // 32 node groups x 4 nodes
    int nodeBase = blockIdx.x * 128;

    float acc[4][8];
#pragma unroll
    for (int a = 0; a < 4; a++)
#pragma unroll
        for (int b = 0; b < 8; b++) acc[a][b] = 0.0f;

    for (int k0 = 0; k0 < KDIM; k0 += 32) {
        __syncthreads();
        for (int i = tid; i < 32 * 64; i += 256)
            Ws[i] = W[(k0 + (i >> 6)) * 64 + (i & 63)];
        for (int i = tid; i < 128 * 32; i += 256) {
            int node = i >> 5, kk = i & 31;
            int gn = nodeBase + node;
            if (gn >= N_NODES) gn = N_NODES - 1;
            Xs[node * 33 + kk] = x[(size_t)gn * KDIM + k0 + kk];
        }
        __syncthreads();
#pragma unroll
        for (int kk = 0; kk < 32; kk++) {
            float4 w0 = *reinterpret_cast<const float4*>(&Ws[kk * 64 + fgrp * 8]);
            float4 w1 = *reinterpret_cast<const float4*>(&Ws[kk * 64 + fgrp * 8 + 4]);
#pragma unroll
            for (int nn = 0; nn < 4; nn++) {
                float xv = Xs[(ngrp * 4 + nn) * 33 + kk];
                acc[nn][0] += xv * w0.x; acc[nn][1] += xv * w0.y;
                acc[nn][2] += xv * w0.z; acc[nn][3] += xv * w0.w;
                acc[nn][4] += xv * w1.x; acc[nn][5] += xv * w1.y;
                acc[nn][6] += xv * w1.z; acc[nn][7] += xv * w1.w;
            }
        }
    }

#pragma unroll
    for (int nn = 0; nn < 4; nn++) {
        int n = nodeBase + ngrp * 4 + nn;
        if (n < N_NODES) {
            float4* o = reinterpret_cast<float4*>(out + (size_t)n * 64 + fgrp * 8);
            o[0] = make_float4(acc[nn][0], acc[nn][1], acc[nn][2], acc[nn][3]);
            o[1] = make_float4(acc[nn][4], acc[nn][5], acc[nn][6], acc[nn][7]);
        }
    }
}

// ------------------------- fused gather + self + BN + ReLU (+ head) --------
// One warp per node. lane covers features lane and lane+32.
template <bool HEAD>
__global__ void k_gather(const float* __restrict__ h,
                         const float* __restrict__ bb, const float* __restrict__ gg,
                         const float* __restrict__ be, const float* __restrict__ mm,
                         const float* __restrict__ vv,
                         const float* __restrict__ Wc1, const float* __restrict__ bc1,
                         const float* __restrict__ Wc2, const float* __restrict__ bc2,
                         float* __restrict__ out) {
    __shared__ float W1s[64 * 32];
    int tid = threadIdx.x, lane = tid & 31, warp = tid >> 5;
    if (HEAD) {
        for (int i = tid; i < 64 * 32; i += 256) W1s[i] = Wc1[i];
        __syncthreads();
    }
    int n = blockIdx.x * 8 + warp;
    if (n >= N_NODES) return;

    int beg = g_rowptr[n], end = g_rowptr[n + 1];
    float di = g_dinv[n];
    const float* hn = h + (size_t)n * 64;
    float acc0 = di * di * __ldg(hn + lane);
    float acc1 = di * di * __ldg(hn + 32 + lane);

    // chunks of 16 edges, padded lanes contribute 0
    for (int p = beg; p < end; p += 16) {
        int idx = p + lane;
        bool v = (lane < 16) && (idx < end);
        int s   = v ? __ldg(g_esrc + idx) : 0;
        float w = v ? __ldg(g_ew + idx) : 0.0f;
#pragma unroll
        for (int j = 0; j < 16; j++) {
            int ss  = __shfl_sync(0xffffffffu, s, j);
            float ww = __shfl_sync(0xffffffffu, w, j);
            const float* hs = h + (size_t)ss * 64;
            acc0 += ww * __ldg(hs + lane);
            acc1 += ww * __ldg(hs + 32 + lane);
        }
    }

    // bias + BN + ReLU
    float sc0 = __ldg(gg + lane) * rsqrtf(__ldg(vv + lane) + BN_EPS);
    float sc1 = __ldg(gg + 32 + lane) * rsqrtf(__ldg(vv + 32 + lane) + BN_EPS);
    float val0 = fmaxf((acc0 + __ldg(bb + lane) - __ldg(mm + lane)) * sc0 + __ldg(be + lane), 0.0f);
    float val1 = fmaxf((acc1 + __ldg(bb + 32 + lane) - __ldg(mm + 32 + lane)) * sc1 + __ldg(be + 32 + lane), 0.0f);

    if (!HEAD) {
        out[(size_t)n * 64 + lane]      = val0;
        out[(size_t)n * 64 + 32 + lane] = val1;
    } else {
        float a = __ldg(bc1 + lane);
#pragma unroll
        for (int k = 0; k < 32; k++)
            a += __shfl_sync(0xffffffffu, val0, k) * W1s[k * 32 + lane];
#pragma unroll
        for (int k = 0; k < 32; k++)
            a += __shfl_sync(0xffffffffu, val1, k) * W1s[(32 + k) * 32 + lane];
        float mid = fmaxf(a, 0.0f);
        float pp = mid * __ldg(Wc2 + lane);
#pragma unroll
        for (int off = 16; off; off >>= 1)
            pp += __shfl_xor_sync(0xffffffffu, pp, off);
        if (lane == 0)
            out[n] = 1.0f / (1.0f + expf(-(pp + __ldg(bc2))));
    }
}

// ---------------------------------------------------------------------------
extern "C" void kernel_launch(void* const* d_in, const int* in_sizes, int n_in,
                              void* d_out, int out_size) {
    const float* x   = (const float*)d_in[0];
    const int*   ei  = (const int*)  d_in[1];
    const float* W1  = (const float*)d_in[2];
    const float* b1  = (const float*)d_in[3];
    const float* g1  = (const float*)d_in[4];
    const float* be1 = (const float*)d_in[5];
    const float* m1  = (const float*)d_in[6];
    const float* v1  = (const float*)d_in[7];
    const float* W2  = (const float*)d_in[8];
    const float* b2  = (const float*)d_in[9];
    const float* g2  = (const float*)d_in[10];
    const float* be2 = (const float*)d_in[11];
    const float* m2  = (const float*)d_in[12];
    const float* v2  = (const float*)d_in[13];
    const float* Wc1 = (const float*)d_in[14];
    const float* bc1 = (const float*)d_in[15];
    const float* Wc2 = (const float*)d_in[16];
    const float* bc2 = (const float*)d_in[17];
    float* out = (float*)d_out;

    float* bufA;  cudaGetSymbolAddress((void**)&bufA, g_bufA);
    float* bufB;  cudaGetSymbolAddress((void**)&bufB, g_bufB);

    const int nodeBlocks = (N_NODES + 255) / 256;            // 391
    const int edgeBlocks = (N_EDGES + 255) / 256;            // 6250
    const int scanBlocks = (N_NODES + 1023) / 1024;          // 98
    const int gemmBlocks = (N_NODES + 127) / 128;            // 782
    const int gathBlocks = (N_NODES + 7) / 8;                // 12500

    // CSR build (shared by both layers)
    k_zero_cnt<<<nodeBlocks, 256>>>();
    k_hist<<<edgeBlocks, 256>>>(ei);
    k_dinv<<<nodeBlocks, 256>>>();
    k_scan1<<<scanBlocks, 1024>>>();
    k_scan2<<<1, 128>>>(scanBlocks);
    k_scan3<<<nodeBlocks, 256>>>();
    k_cursor<<<nodeBlocks, 256>>>();
    k_fill<<<edgeBlocks, 256>>>(ei);

    // layer 1
    k_gemm<F_IN><<<gemmBlocks, 256>>>(x, W1, bufA);
    k_gather<false><<<gathBlocks, 256>>>(bufA, b1, g1, be1, m1, v1,
                                         nullptr, nullptr, nullptr, nullptr, bufB);
    // layer 2 + head (fused)
    k_gemm<F_HID><<<gemmBlocks, 256>>>(bufB, W2, bufA);
    k_gather<true><<<gathBlocks, 256>>>(bufA, b2, g2, be2, m2, v2,
                                        Wc1, bc1, Wc2, bc2, out);
}

// round 3
// speedup vs baseline: 2.1286x; 1.0466x over previous
#include <cuda_runtime.h>
#include <math.h>

#define N_NODES 100000
#define N_EDGES 1600000
#define F_IN    128
#define F_HID   64
#define BN_EPS  1e-5f

// ------------------------- scratch (__device__ globals) --------------------
__device__ float g_bufA[(size_t)N_NODES * F_HID];   // 25.6 MB
__device__ float g_bufB[(size_t)N_NODES * F_HID];   // 25.6 MB
__device__ float g_dinv[N_NODES];
__device__ int   g_cnt[N_NODES];
__device__ int   g_rowptr[N_NODES + 1];
__device__ int   g_cursor[N_NODES];
__device__ int2  g_epair[N_EDGES];                  // (src, norm-as-int)
__device__ int   g_blksum[128];

// ------------------------- degree / CSR build ------------------------------
__global__ void k_zero_cnt() {
    int i = blockIdx.x * blockDim.x + threadIdx.x;
    if (i < N_NODES) g_cnt[i] = 0;
}

__global__ void k_hist(const int* __restrict__ ei) {
    int e = blockIdx.x * blockDim.x + threadIdx.x;
    if (e < N_EDGES) atomicAdd(&g_cnt[ei[N_EDGES + e]], 1);
}

// per-block inclusive scan of g_cnt -> g_rowptr[i+1]; also dinv = rsqrt(cnt+1)
__global__ void k_scan1() {
    __shared__ int wsum[32];
    int i = blockIdx.x * 1024 + threadIdx.x;
    int lane = threadIdx.x & 31, wid = threadIdx.x >> 5;
    int v = (i < N_NODES) ? g_cnt[i] : 0;
    if (i < N_NODES) g_dinv[i] = rsqrtf((float)v + 1.0f);
    int sv = v;
#pragma unroll
    for (int d = 1; d < 32; d <<= 1) {
        int t = __shfl_up_sync(0xffffffffu, sv, d);
        if (lane >= d) sv += t;
    }
    if (lane == 31) wsum[wid] = sv;
    __syncthreads();
    if (wid == 0) {
        int wv = wsum[lane];
#pragma unroll
        for (int d = 1; d < 32; d <<= 1) {
            int t = __shfl_up_sync(0xffffffffu, wv, d);
            if (lane >= d) wv += t;
        }
        wsum[lane] = wv;
    }
    __syncthreads();
    int incl = sv + (wid > 0 ? wsum[wid - 1] : 0);
    if (i < N_NODES) g_rowptr[i + 1] = incl;
    if (threadIdx.x == 1023) g_blksum[blockIdx.x] = incl;
}

__global__ void k_scan2(int nb) {
    __shared__ int wsum[4];
    int b = threadIdx.x;
    int lane = b & 31, wid = b >> 5;
    int v = (b < nb) ? g_blksum[b] : 0;
    int sv = v;
#pragma unroll
    for (int d = 1; d < 32; d <<= 1) {
        int t = __shfl_up_sync(0xffffffffu, sv, d);
        if (lane >= d) sv += t;
    }
    if (lane == 31) wsum[wid] = sv;
    __syncthreads();
    if (b == 0) {
        int run = 0;
#pragma unroll
        for (int w = 0; w < 4; w++) { int t = wsum[w]; wsum[w] = run; run += t; }
    }
    __syncthreads();
    int excl = sv + wsum[wid] - v;
    if (b < nb) g_blksum[b] = excl;
}

// finalize rowptr and init cursor
__global__ void k_scan3() {
    int i = blockIdx.x * blockDim.x + threadIdx.x;
    if (i < N_NODES) {
        int rp = g_rowptr[i + 1] + g_blksum[i >> 10];
        g_rowptr[i + 1] = rp;
    }
    if (i == 0) g_rowptr[0] = 0;
}

__global__ void k_cursor() {
    int i = blockIdx.x * blockDim.x + threadIdx.x;
    if (i < N_NODES) g_cursor[i] = g_rowptr[i];
}

__global__ void k_fill(const int* __restrict__ ei) {
    int e = blockIdx.x * blockDim.x + threadIdx.x;
    if (e >= N_EDGES) return;
    int s = ei[e];
    int d = ei[N_EDGES + e];
    int pos = atomicAdd(&g_cursor[d], 1);
    float w = g_dinv[s] * g_dinv[d];
    g_epair[pos] = make_int2(s, __float_as_int(w));
}

// ------------------------- GEMM: out[N,64] = x[N,KDIM] @ W[KDIM,64] --------
template <int KDIM>
__global__ void k_gemm(const float* __restrict__ x,
                       const float* __restrict__ W,
                       float* __restrict__ out) {
    __shared__ float Ws[32 * 64];
    __shared__ float Xs[128 * 33];

    int tid  = threadIdx.x;
    int fgrp = tid & 7;
    int ngrp = tid >> 3;
    int nodeBase = blockIdx.x * 128;

    float acc[4][8];
#pragma unroll
    for (int a = 0; a < 4; a++)
#pragma unroll
        for (int b = 0; b < 8; b++) acc[a][b] = 0.0f;

    for (int k0 = 0; k0 < KDIM; k0 += 32) {
        __syncthreads();
        for (int i = tid; i < 32 * 64; i += 256)
            Ws[i] = W[(k0 + (i >> 6)) * 64 + (i & 63)];
        for (int i = tid; i < 128 * 32; i += 256) {
            int node = i >> 5, kk = i & 31;
            int gn = nodeBase + node;
            if (gn >= N_NODES) gn = N_NODES - 1;
            Xs[node * 33 + kk] = x[(size_t)gn * KDIM + k0 + kk];
        }
        __syncthreads();
#pragma unroll
        for (int kk = 0; kk < 32; kk++) {
            float4 w0 = *reinterpret_cast<const float4*>(&Ws[kk * 64 + fgrp * 8]);
            float4 w1 = *reinterpret_cast<const float4*>(&Ws[kk * 64 + fgrp * 8 + 4]);
#pragma unroll
            for (int nn = 0; nn < 4; nn++) {
                float xv = Xs[(ngrp * 4 + nn) * 33 + kk];
                acc[nn][0] += xv * w0.x; acc[nn][1] += xv * w0.y;
                acc[nn][2] += xv * w0.z; acc[nn][3] += xv * w0.w;
                acc[nn][4] += xv * w1.x; acc[nn][5] += xv * w1.y;
                acc[nn][6] += xv * w1.z; acc[nn][7] += xv * w1.w;
            }
        }
    }

#pragma unroll
    for (int nn = 0; nn < 4; nn++) {
        int n = nodeBase + ngrp * 4 + nn;
        if (n < N_NODES) {
            float4* o = reinterpret_cast<float4*>(out + (size_t)n * 64 + fgrp * 8);
            o[0] = make_float4(acc[nn][0], acc[nn][1], acc[nn][2], acc[nn][3]);
            o[1] = make_float4(acc[nn][4], acc[nn][5], acc[nn][6], acc[nn][7]);
        }
    }
}

// ------------------------- fused gather + self + BN + ReLU (+ head) --------
// One warp per node. Lane holds features (2*lane, 2*lane+1) as float2.
template <bool HEAD>
__global__ void k_gather(const float* __restrict__ h,
                         const float* __restrict__ bb, const float* __restrict__ gg,
                         const float* __restrict__ be, const float* __restrict__ mm,
                         const float* __restrict__ vv,
                         const float* __restrict__ Wc1, const float* __restrict__ bc1,
                         const float* __restrict__ Wc2, const float* __restrict__ bc2,
                         float* __restrict__ out) {
    __shared__ float W1s[64 * 32];
    int tid = threadIdx.x, lane = tid & 31, warp = tid >> 5;
    if (HEAD) {
        for (int i = tid; i < 64 * 32; i += 256) W1s[i] = Wc1[i];
        __syncthreads();
    }
    int n = blockIdx.x * 8 + warp;
    if (n >= N_NODES) return;

    const float2* __restrict__ h2 = reinterpret_cast<const float2*>(h);
    int beg = g_rowptr[n], end = g_rowptr[n + 1];
    float di = g_dinv[n];

    float2 hv = __ldg(h2 + (size_t)n * 32 + lane);
    float accx = di * di * hv.x;
    float accy = di * di * hv.y;

    for (int p = beg; p < end; p += 8) {
        int2 eb[8];
#pragma unroll
        for (int j = 0; j < 8; j++) {
            int idx = p + j;
            eb[j] = (idx < end) ? __ldg(&g_epair[idx]) : make_int2(0, 0);
        }
#pragma unroll
        for (int j = 0; j < 8; j++) {
            float w = __int_as_float(eb[j].y);
            float2 hs = __ldg(h2 + (size_t)eb[j].x * 32 + lane);
            accx += w * hs.x;
            accy += w * hs.y;
        }
    }

    // bias + BN + ReLU for feats f0 = 2*lane, f1 = 2*lane+1
    int f0 = 2 * lane, f1 = 2 * lane + 1;
    float sc0 = __ldg(gg + f0) * rsqrtf(__ldg(vv + f0) + BN_EPS);
    float sc1 = __ldg(gg + f1) * rsqrtf(__ldg(vv + f1) + BN_EPS);
    float val0 = fmaxf((accx + __ldg(bb + f0) - __ldg(mm + f0)) * sc0 + __ldg(be + f0), 0.0f);
    float val1 = fmaxf((accy + __ldg(bb + f1) - __ldg(mm + f1)) * sc1 + __ldg(be + f1), 0.0f);

    if (!HEAD) {
        reinterpret_cast<float2*>(out)[(size_t)n * 32 + lane] = make_float2(val0, val1);
    } else {
        // mid[j] = relu(sum_k val[k] * Wc1[k,j] + bc1[j]); feat 2k from lane k val0
        float a = __ldg(bc1 + lane);
#pragma unroll
        for (int k = 0; k < 32; k++) {
            a += __shfl_sync(0xffffffffu, val0, k) * W1s[(2 * k)     * 32 + lane];
            a += __shfl_sync(0xffffffffu, val1, k) * W1s[(2 * k + 1) * 32 + lane];
        }
        float mid = fmaxf(a, 0.0f);
        float pp = mid * __ldg(Wc2 + lane);
#pragma unroll
        for (int off = 16; off; off >>= 1)
            pp += __shfl_xor_sync(0xffffffffu, pp, off);
        if (lane == 0)
            out[n] = 1.0f / (1.0f + expf(-(pp + __ldg(bc2))));
    }
}

// ---------------------------------------------------------------------------
extern "C" void kernel_launch(void* const* d_in, const int* in_sizes, int n_in,
                              void* d_out, int out_size) {
    const float* x   = (const float*)d_in[0];
    const int*   ei  = (const int*)  d_in[1];
    const float* W1  = (const float*)d_in[2];
    const float* b1  = (const float*)d_in[3];
    const float* g1  = (const float*)d_in[4];
    const float* be1 = (const float*)d_in[5];
    const float* m1  = (const float*)d_in[6];
    const float* v1  = (const float*)d_in[7];
    const float* W2  = (const float*)d_in[8];
    const float* b2  = (const float*)d_in[9];
    const float* g2  = (const float*)d_in[10];
    const float* be2 = (const float*)d_in[11];
    const float* m2  = (const float*)d_in[12];
    const float* v2  = (const float*)d_in[13];
    const float* Wc1 = (const float*)d_in[14];
    const float* bc1 = (const float*)d_in[15];
    const float* Wc2 = (const float*)d_in[16];
    const float* bc2 = (const float*)d_in[17];
    float* out = (float*)d_out;

    float* bufA;  cudaGetSymbolAddress((void**)&bufA, g_bufA);
    float* bufB;  cudaGetSymbolAddress((void**)&bufB, g_bufB);

    const int nodeBlocks = (N_NODES + 255) / 256;            // 391
    const int edgeBlocks = (N_EDGES + 255) / 256;            // 6250
    const int scanBlocks = (N_NODES + 1023) / 1024;          // 98
    const int gemmBlocks = (N_NODES + 127) / 128;            // 782
    const int gathBlocks = (N_NODES + 7) / 8;                // 12500

    // CSR build (shared by both layers)
    k_zero_cnt<<<nodeBlocks, 256>>>();
    k_hist<<<edgeBlocks, 256>>>(ei);
    k_scan1<<<scanBlocks, 1024>>>();
    k_scan2<<<1, 128>>>(scanBlocks);
    k_scan3<<<nodeBlocks, 256>>>();
    k_cursor<<<nodeBlocks, 256>>>();
    k_fill<<<edgeBlocks, 256>>>(ei);

    // layer 1
    k_gemm<F_IN><<<gemmBlocks, 256>>>(x, W1, bufA);
    k_gather<false><<<gathBlocks, 256>>>(bufA, b1, g1, be1, m1, v1,
                                         nullptr, nullptr, nullptr, nullptr, bufB);
    // layer 2 + head (fused)
    k_gemm<F_HID><<<gemmBlocks, 256>>>(bufB, W2, bufA);
    k_gather<true><<<gathBlocks, 256>>>(bufA, b2, g2, be2, m2, v2,
                                        Wc1, bc1, Wc2, bc2, out);
}